// round 1
// baseline (speedup 1.0000x reference)
#include <cuda_runtime.h>
#include <cuda_bf16.h>
#include <math.h>

// ---------------------------------------------------------------------------
// Problem constants
// ---------------------------------------------------------------------------
#define BATCH 4
#define IMG_H 512
#define IMG_W 1408
#define H1 256
#define W1p 704
#define H2 128
#define W2p 352
#define FH 64
#define FW 176
#define NPIX (FH*FW)            // 11264
#define HM_SZ (BATCH*NPIX)      // 45056
#define BEV 512
#define BEV_SZ (BATCH*BEV*BEV)  // 1048576
#define TOPK 200
#define THR 0.15f
#define EPSV 1e-4f

#define OFF_HM     0
#define OFF_DEPTH  (HM_SZ)
#define OFF_LOGITS (2*HM_SZ)
#define OFF_PROB   (2*HM_SZ + BEV_SZ)

// ---------------------------------------------------------------------------
// Scratch buffers (device globals — no allocation allowed)
// ---------------------------------------------------------------------------
__device__ float g_x1[BATCH*32*H1*W1p];     // after conv1
__device__ float g_x2[BATCH*64*H2*W2p];     // after conv2
__device__ float g_feats[BATCH*96*FH*FW];   // after conv3
__device__ float g_h1[BATCH*96*FH*FW];      // heatmap head hidden
__device__ float g_d1[BATCH*96*FH*FW];      // depth head hidden

// ---------------------------------------------------------------------------
// Generic direct 3x3 conv + BN(eval) + ReLU.
// One thread: one (b, oy, ox), OCPT output channels. Weights in SMEM.
// ---------------------------------------------------------------------------
template<int IC, int OC, int OCPT, int STRIDE>
__global__ void conv3x3_bnrelu(const float* __restrict__ in,
                               const float* __restrict__ wgt,
                               const float* __restrict__ gamma,
                               const float* __restrict__ beta,
                               float* __restrict__ out,
                               int IH, int IW, int OH, int OW)
{
    constexpr int NG = OC / OCPT;
    const int b  = blockIdx.z / NG;
    const int g  = blockIdx.z % NG;
    const int oy = blockIdx.y;
    const int ox = blockIdx.x * blockDim.x + threadIdx.x;

    __shared__ float ws[OCPT * IC * 9];
    for (int i = threadIdx.x; i < OCPT * IC * 9; i += blockDim.x)
        ws[i] = wgt[(size_t)(g * OCPT) * IC * 9 + i];
    __syncthreads();
    if (ox >= OW) return;

    float acc[OCPT];
#pragma unroll
    for (int o = 0; o < OCPT; o++) acc[o] = 0.f;

    const float* inb = in + (size_t)b * IC * IH * IW;
#pragma unroll 1
    for (int ic = 0; ic < IC; ic++) {
        const float* inc = inb + (size_t)ic * IH * IW;
#pragma unroll
        for (int ky = 0; ky < 3; ky++) {
            const int iy = oy * STRIDE - 1 + ky;
            if (iy < 0 || iy >= IH) continue;
#pragma unroll
            for (int kx = 0; kx < 3; kx++) {
                const int ix = ox * STRIDE - 1 + kx;
                if (ix < 0 || ix >= IW) continue;
                const float v = inc[(size_t)iy * IW + ix];
#pragma unroll
                for (int o = 0; o < OCPT; o++)
                    acc[o] += v * ws[(o * IC + ic) * 9 + ky * 3 + kx];
            }
        }
    }

    const float inv = rsqrtf(1.f + 1e-5f);
    const size_t outbase = ((size_t)b * OC + g * OCPT) * OH * OW + (size_t)oy * OW + ox;
#pragma unroll
    for (int o = 0; o < OCPT; o++) {
        const int oc = g * OCPT + o;
        float v = acc[o] * (gamma[oc] * inv) + beta[oc];
        out[outbase + (size_t)o * OH * OW] = fmaxf(v, 0.f);
    }
}

// ---------------------------------------------------------------------------
// 1x1 conv (96 -> 1) + bias.  mode 0: raw logits (hm). mode 1: depth transform.
// ---------------------------------------------------------------------------
template<int MODE>
__global__ void head1x1(const float* __restrict__ feat,
                        const float* __restrict__ w,
                        const float* __restrict__ bias,
                        float* __restrict__ out)
{
    const int idx = blockIdx.x * blockDim.x + threadIdx.x;
    if (idx >= BATCH * NPIX) return;
    const int b = idx / NPIX;
    const int p = idx % NPIX;
    float s = bias[0];
    const float* fb = feat + (size_t)b * 96 * NPIX + p;
#pragma unroll 8
    for (int ic = 0; ic < 96; ic++)
        s += fb[(size_t)ic * NPIX] * w[ic];
    if (MODE == 0) {
        out[idx] = s;
    } else {
        const float sig = 1.f / (1.f + expf(-s));
        out[idx] = 1.0f + sig * 79.0f;   // DMIN + sig*(DMAX-DMIN)
    }
}

// ---------------------------------------------------------------------------
// Zero the BEV accumulation region
// ---------------------------------------------------------------------------
__global__ void zero_bev(float* __restrict__ bev)
{
    const int i = blockIdx.x * blockDim.x + threadIdx.x;
    if (i < BEV_SZ) bev[i] = 0.f;
}

// ---------------------------------------------------------------------------
// Per-batch top-200 (iterative block argmax, lowest-index tie break) + splat.
// One block per batch, 1024 threads.
// ---------------------------------------------------------------------------
__global__ void __launch_bounds__(1024, 1)
topk_splat(const float* __restrict__ hm,     // d_out + OFF_HM
           const float* __restrict__ depth,  // d_out + OFF_DEPTH
           const float* __restrict__ P,      // camera_projection [B,3,4]
           const float* __restrict__ T,      // t_lidar_camera   [B,4,4]
           float* __restrict__ bev)          // d_out + OFF_PROB (accumulator)
{
    const int b    = blockIdx.x;
    const int tid  = threadIdx.x;
    const int lane = tid & 31;
    const int warp = tid >> 5;

    __shared__ float prob[NPIX];
    __shared__ float sscore[TOPK];
    __shared__ int   sidx[TOPK];
    __shared__ float wv[32];
    __shared__ int   wi[32];

    for (int i = tid; i < NPIX; i += blockDim.x) {
        const float x = hm[b * NPIX + i];
        prob[i] = 1.f / (1.f + expf(-x));
    }
    __syncthreads();

    for (int k = 0; k < TOPK; k++) {
        float v = -1.f; int bi = NPIX;
        for (int i = tid; i < NPIX; i += blockDim.x) {
            const float p = prob[i];
            if (p > v || (p == v && i < bi)) { v = p; bi = i; }
        }
#pragma unroll
        for (int off = 16; off > 0; off >>= 1) {
            const float ov = __shfl_down_sync(0xffffffffu, v, off);
            const int   oi = __shfl_down_sync(0xffffffffu, bi, off);
            if (ov > v || (ov == v && oi < bi)) { v = ov; bi = oi; }
        }
        if (lane == 0) { wv[warp] = v; wi[warp] = bi; }
        __syncthreads();
        if (warp == 0) {
            v  = wv[lane];
            bi = wi[lane];
#pragma unroll
            for (int off = 16; off > 0; off >>= 1) {
                const float ov = __shfl_down_sync(0xffffffffu, v, off);
                const int   oi = __shfl_down_sync(0xffffffffu, bi, off);
                if (ov > v || (ov == v && oi < bi)) { v = ov; bi = oi; }
            }
            if (lane == 0) {
                sscore[k] = v;
                sidx[k]   = bi;
                prob[bi]  = -1.f;   // mark used
            }
        }
        __syncthreads();
    }

    // ---- projection + Gaussian max-splat (threads 0..199) ----
    if (tid < TOPK) {
        const int   idx   = sidx[tid];
        const float score = sscore[tid];
        const int ys = idx / FW;
        const int xs = idx % FW;
        const float d = depth[b * NPIX + idx];
        const float u = (xs + 0.5f) * ((float)IMG_W / (float)FW);   // *8
        const float v = (ys + 0.5f) * ((float)IMG_H / (float)FH);   // *8

        const float* Pb = P + b * 12;
        const float fx = fmaxf(Pb[0], EPSV);
        const float fy = fmaxf(Pb[5], EPSV);
        const float cx = Pb[2], cy = Pb[6];
        const float tx = Pb[3], ty = Pb[7];
        const float xc = (u * d - cx * d - tx) / fx;
        const float yc = (v * d - cy * d - ty) / fy;

        const float* Tb = T + b * 16;
        const float lx = Tb[0]*xc + Tb[1]*yc + Tb[2]*d + Tb[3];
        const float ly = Tb[4]*xc + Tb[5]*yc + Tb[6]*d + Tb[7];

        const int gx = (int)floorf((lx + 51.2f) / 0.2f);
        const int gy = (int)floorf((ly + 51.2f) / 0.2f);

        const bool valid = (score >= THR) && (gx >= 0) && (gx < BEV)
                                          && (gy >= 0) && (gy < BEV);
        if (valid) {
            // sigma = 5/6  =>  1/(2*sigma^2) = 18/25
            const float isig = 18.f / 25.f;
            float* bb = bev + (size_t)b * BEV * BEV;
#pragma unroll
            for (int dy = -2; dy <= 2; dy++) {
                const int iy = gy + dy;
                if (iy < 0 || iy >= BEV) continue;
#pragma unroll
                for (int dx = -2; dx <= 2; dx++) {
                    const int ix = gx + dx;
                    if (ix < 0 || ix >= BEV) continue;
                    const float val = score * expf(-(float)(dy*dy + dx*dx) * isig);
                    atomicMax((int*)&bb[iy * BEV + ix], __float_as_int(val));
                }
            }
        }
    }
}

// ---------------------------------------------------------------------------
// Finalize: clip to prob, compute logits. (prob region holds raw bev max)
// ---------------------------------------------------------------------------
__global__ void finalize_bev(float* __restrict__ out)
{
    const int i = blockIdx.x * blockDim.x + threadIdx.x;
    if (i >= BEV_SZ) return;
    float p = out[OFF_PROB + i];
    p = fminf(fmaxf(p, EPSV), 1.f - EPSV);
    out[OFF_PROB + i]   = p;
    out[OFF_LOGITS + i] = logf(p) - log1pf(-p);
}

// ---------------------------------------------------------------------------
// Launcher
// ---------------------------------------------------------------------------
extern "C" void kernel_launch(void* const* d_in, const int* in_sizes, int n_in,
                              void* d_out, int out_size)
{
    (void)in_sizes; (void)n_in; (void)out_size;

    const float* image = (const float*)d_in[0];
    const float* P     = (const float*)d_in[1];
    const float* T     = (const float*)d_in[2];
    const float* W1  = (const float*)d_in[3];
    const float* g1  = (const float*)d_in[4];
    const float* b1  = (const float*)d_in[5];
    const float* W2  = (const float*)d_in[6];
    const float* g2  = (const float*)d_in[7];
    const float* b2  = (const float*)d_in[8];
    const float* W3  = (const float*)d_in[9];
    const float* g3  = (const float*)d_in[10];
    const float* b3  = (const float*)d_in[11];
    const float* Wh1 = (const float*)d_in[12];
    const float* gh1 = (const float*)d_in[13];
    const float* bh1 = (const float*)d_in[14];
    const float* Wh2 = (const float*)d_in[15];
    const float* bh2 = (const float*)d_in[16];
    const float* Wd1 = (const float*)d_in[17];
    const float* gd1 = (const float*)d_in[18];
    const float* bd1 = (const float*)d_in[19];
    const float* Wd2 = (const float*)d_in[20];
    const float* bd2 = (const float*)d_in[21];

    float* out = (float*)d_out;

    float *x1, *x2, *feats, *h1, *d1;
    cudaGetSymbolAddress((void**)&x1,    g_x1);
    cudaGetSymbolAddress((void**)&x2,    g_x2);
    cudaGetSymbolAddress((void**)&feats, g_feats);
    cudaGetSymbolAddress((void**)&h1,    g_h1);
    cudaGetSymbolAddress((void**)&d1,    g_d1);

    // conv1: 3 -> 32, stride 2   (512x1408 -> 256x704)
    {
        dim3 blk(128);
        dim3 grd((W1p + 127) / 128, H1, BATCH * (32 / 32));
        conv3x3_bnrelu<3, 32, 32, 2><<<grd, blk>>>(image, W1, g1, b1, x1,
                                                   IMG_H, IMG_W, H1, W1p);
    }
    // conv2: 32 -> 64, stride 2  (256x704 -> 128x352)
    {
        dim3 blk(128);
        dim3 grd((W2p + 127) / 128, H2, BATCH * (64 / 16));
        conv3x3_bnrelu<32, 64, 16, 2><<<grd, blk>>>(x1, W2, g2, b2, x2,
                                                    H1, W1p, H2, W2p);
    }
    // conv3: 64 -> 96, stride 2  (128x352 -> 64x176)
    {
        dim3 blk(192);
        dim3 grd(1, FH, BATCH * (96 / 16));
        conv3x3_bnrelu<64, 96, 16, 2><<<grd, blk>>>(x2, W3, g3, b3, feats,
                                                    H2, W2p, FH, FW);
    }
    // hm head hidden: 96 -> 96, stride 1, pad 1
    {
        dim3 blk(192);
        dim3 grd(1, FH, BATCH * (96 / 8));
        conv3x3_bnrelu<96, 96, 8, 1><<<grd, blk>>>(feats, Wh1, gh1, bh1, h1,
                                                   FH, FW, FH, FW);
    }
    // hm 1x1 -> d_out[OFF_HM]
    head1x1<0><<<(BATCH * NPIX + 255) / 256, 256>>>(h1, Wh2, bh2, out + OFF_HM);

    // depth head hidden: 96 -> 96, stride 1, pad 1
    {
        dim3 blk(192);
        dim3 grd(1, FH, BATCH * (96 / 8));
        conv3x3_bnrelu<96, 96, 8, 1><<<grd, blk>>>(feats, Wd1, gd1, bd1, d1,
                                                   FH, FW, FH, FW);
    }
    // depth 1x1 + transform -> d_out[OFF_DEPTH]
    head1x1<1><<<(BATCH * NPIX + 255) / 256, 256>>>(d1, Wd2, bd2, out + OFF_DEPTH);

    // BEV accumulate (prob region), splat, finalize
    zero_bev<<<(BEV_SZ + 255) / 256, 256>>>(out + OFF_PROB);
    topk_splat<<<BATCH, 1024>>>(out + OFF_HM, out + OFF_DEPTH, P, T, out + OFF_PROB);
    finalize_bev<<<(BEV_SZ + 255) / 256, 256>>>(out);
}